// round 12
// baseline (speedup 1.0000x reference)
#include <cuda_runtime.h>

#define HW     4096
#define WIDTH  64
#define CDIM   256
#define NH     8
#define HD     32
#define BATCH  2
#define SCALE  0.17677669529663687f

// Scratch (device globals; no allocation allowed)
__device__ float g_q[BATCH * NH * HW * HD];      // [b, head, p, d]
__device__ float g_k[BATCH * NH * HW * HD];      // [b, head, p, d]
__device__ float g_v[BATCH * NH * HW * HD];      // [b, head, p, d]
__device__ float g_attn[BATCH * HW * CDIM];      // [b, p, c]  c = head*32+d

// ---------------------------------------------------------------------------
// tf32 MMA helpers
// ---------------------------------------------------------------------------
__device__ __forceinline__ unsigned f2tf(float f)
{
    unsigned u;
    asm("cvt.rna.tf32.f32 %0, %1;" : "=r"(u) : "f"(f));
    return u;
}

__device__ __forceinline__ uint4 f2tf4(float4 v)
{
    uint4 u;
    u.x = f2tf(v.x); u.y = f2tf(v.y); u.z = f2tf(v.z); u.w = f2tf(v.w);
    return u;
}

__device__ __forceinline__ void mma8(float d[4], const unsigned a[4], const unsigned b[2])
{
    asm("mma.sync.aligned.m16n8k8.row.col.f32.tf32.tf32.f32 "
        "{%0,%1,%2,%3}, {%4,%5,%6,%7}, {%8,%9}, {%0,%1,%2,%3};"
        : "+f"(d[0]), "+f"(d[1]), "+f"(d[2]), "+f"(d[3])
        : "r"(a[0]), "r"(a[1]), "r"(a[2]), "r"(a[3]),
          "r"(b[0]), "r"(b[1]));
}

// ---------------------------------------------------------------------------
// Kernel 1: QKV projection, tf32, 64x64 tile, k-chunk 32 (proven R8 config).
// Epilogue stages the accumulator tile through smem (aliased onto As/Bs) so
// global stores are coalesced STG.128 along d instead of scattered STG.32.
// ---------------------------------------------------------------------------
struct QkvLoadBufs { unsigned As[64][36]; unsigned Bs[32][72]; };
union QkvSmem { QkvLoadBufs ld; float Cs[64][66]; };

__global__ __launch_bounds__(256) void qkv_gemm_kernel(
    const float* __restrict__ x,
    const float* __restrict__ w0, const float* __restrict__ bb0,
    const float* __restrict__ w1, const float* __restrict__ bb1,
    const float* __restrict__ w2, const float* __restrict__ bb2)
{
    __shared__ QkvSmem su;
    __shared__ const float* Arow[64];
    __shared__ float* rowDst[64];
    __shared__ float biasS[64];

    const int tid  = threadIdx.x;
    const int row0 = blockIdx.y * 64;
    const int col0 = blockIdx.x * 64;
    const int b    = blockIdx.z;

    if (tid < 64) {
        int M = row0 + tid;
        int t = M >> 8;
        int rem = M & 255;
        int head = rem >> 5, d = rem & 31;
        const float* w; const float* bb;
        if (head < 4)      { w = w0; bb = bb0; }
        else if (head < 7) { w = w1; bb = bb1; }
        else               { w = w2; bb = bb2; }
        Arow[tid]  = w + (size_t)(t * 256 + rem) * 256;
        biasS[tid] = bb[t * 256 + rem];
        float* dst = (t == 0) ? g_q : (t == 1) ? g_k : g_v;
        rowDst[tid] = dst + ((size_t)(b * NH + head) * HW) * HD + d;
    }
    __syncthreads();

    const int wid  = tid >> 5;
    const int lane = tid & 31;
    const int g = lane >> 2, t4 = lane & 3;
    const int m0 = (wid >> 2) * 32;
    const int n0 = (wid & 3) * 16;

    const int am = tid >> 2, ak = (tid & 3) * 8;
    const int bk = tid >> 3, bn = (tid & 7) * 8;

    const float* xb = x + (size_t)b * CDIM * HW;
    float acc[2][2][4] = {};

    for (int k0 = 0; k0 < 256; k0 += 32) {
        {
            const float* src = Arow[am] + k0 + ak;
            float4 v0 = *(const float4*)(src);
            float4 v1 = *(const float4*)(src + 4);
            *(uint4*)&su.ld.As[am][ak]     = f2tf4(v0);
            *(uint4*)&su.ld.As[am][ak + 4] = f2tf4(v1);
        }
        {
            const float* src = xb + (size_t)(k0 + bk) * HW + col0 + bn;
            float4 v0 = *(const float4*)(src);
            float4 v1 = *(const float4*)(src + 4);
            *(uint4*)&su.ld.Bs[bk][bn]     = f2tf4(v0);
            *(uint4*)&su.ld.Bs[bk][bn + 4] = f2tf4(v1);
        }
        __syncthreads();
        #pragma unroll
        for (int ks = 0; ks < 4; ks++) {
            const int kk = ks * 8;
            unsigned a[2][4], bf[2][2];
            #pragma unroll
            for (int mi = 0; mi < 2; mi++) {
                const int mr = m0 + mi * 16;
                a[mi][0] = su.ld.As[mr + g][kk + t4];
                a[mi][1] = su.ld.As[mr + g + 8][kk + t4];
                a[mi][2] = su.ld.As[mr + g][kk + t4 + 4];
                a[mi][3] = su.ld.As[mr + g + 8][kk + t4 + 4];
            }
            #pragma unroll
            for (int ni = 0; ni < 2; ni++) {
                const int nc = n0 + ni * 8 + g;
                bf[ni][0] = su.ld.Bs[kk + t4][nc];
                bf[ni][1] = su.ld.Bs[kk + t4 + 4][nc];
            }
            #pragma unroll
            for (int mi = 0; mi < 2; mi++)
                #pragma unroll
                for (int ni = 0; ni < 2; ni++)
                    mma8(acc[mi][ni], a[mi], bf[ni]);
        }
        __syncthreads();
    }

    // Stage accumulators to smem (aliases As/Bs; all MMA reads are done).
    #pragma unroll
    for (int mi = 0; mi < 2; mi++) {
        const int mr = m0 + mi * 16;
        #pragma unroll
        for (int ni = 0; ni < 2; ni++) {
            const int pc = n0 + ni * 8 + 2 * t4;
            su.Cs[mr + g][pc]         = acc[mi][ni][0];
            su.Cs[mr + g][pc + 1]     = acc[mi][ni][1];
            su.Cs[mr + g + 8][pc]     = acc[mi][ni][2];
            su.Cs[mr + g + 8][pc + 1] = acc[mi][ni][3];
        }
    }
    __syncthreads();

    // Coalesced global stores: float4 along d. m-quads (m = dq*4) are
    // d-aligned and never cross a head boundary (4 | 32, row0 % 64 == 0).
    #pragma unroll
    for (int i = 0; i < 4; i++) {
        const int f  = tid + 256 * i;
        const int pl = f >> 4;          // local pixel 0..63
        const int m  = (f & 15) * 4;    // m-quad
        float4 v = make_float4(su.Cs[m][pl]     + biasS[m],
                               su.Cs[m + 1][pl] + biasS[m + 1],
                               su.Cs[m + 2][pl] + biasS[m + 2],
                               su.Cs[m + 3][pl] + biasS[m + 3]);
        *(float4*)(rowDst[m] + (size_t)(col0 + pl) * HD) = v;
    }
}

// ---------------------------------------------------------------------------
// Kernel 2: neighborhood attention, quad-pixel warps (proven R8 version).
// One warp = 4 adjacent pixels; 8 lanes per pixel; float4 dims per lane.
// OOB neighbors keep logit = 0 inside the softmax (F.unfold zero padding).
// ---------------------------------------------------------------------------
template <int KSZ, int DIL, bool INTERIOR>
__device__ __forceinline__ void attn_quad(int lane, int b, int head, int p0)
{
    constexpr int L = KSZ * KSZ;
    constexpr int NL8 = (L + 7) / 8;
    constexpr int HALF = KSZ / 2;

    const int r = lane & 7;
    const int g = lane >> 3;
    const int p = p0 + g;
    const int y = p0 >> 6;
    const int x = (p0 & 63) + g;

    const int hb = ((b * NH + head) * HW) * HD;
    const float* __restrict__ kb = g_k + hb;
    const float* __restrict__ vb = g_v + hb;
    const int lo = p * HD + r * 4;

    float4 qv = *(const float4*)(g_q + hb + lo);
    qv.x *= SCALE; qv.y *= SCALE; qv.z *= SCALE; qv.w *= SCALE;

    float lgs[NL8];
    #pragma unroll
    for (int j = 0; j < NL8; j++) lgs[j] = -1e30f;

    const float* __restrict__ kp = kb + lo;

    #pragma unroll
    for (int n = 0; n < L; n++) {
        const int dy = n / KSZ - HALF, dx = n % KSZ - HALF;
        float4 kv;
        if (INTERIOR) {
            kv = *(const float4*)(kp + (dy * 64 + dx) * DIL * HD);
        } else {
            const int ny = y + dy * DIL;
            const int nx = x + dx * DIL;
            if ((unsigned)ny < 64u && (unsigned)nx < 64u)
                kv = *(const float4*)(kb + (ny * 64 + nx) * HD + r * 4);
            else
                kv = make_float4(0.f, 0.f, 0.f, 0.f);
        }
        float s = qv.x * kv.x + qv.y * kv.y + qv.z * kv.z + qv.w * kv.w;
        s += __shfl_xor_sync(0xffffffffu, s, 4);
        s += __shfl_xor_sync(0xffffffffu, s, 2);
        s += __shfl_xor_sync(0xffffffffu, s, 1);
        if (r == (n & 7)) lgs[n >> 3] = s;
    }

    float mx = lgs[0];
    #pragma unroll
    for (int j = 1; j < NL8; j++) mx = fmaxf(mx, lgs[j]);
    mx = fmaxf(mx, __shfl_xor_sync(0xffffffffu, mx, 4));
    mx = fmaxf(mx, __shfl_xor_sync(0xffffffffu, mx, 2));
    mx = fmaxf(mx, __shfl_xor_sync(0xffffffffu, mx, 1));

    float e[NL8];
    float sum = 0.f;
    #pragma unroll
    for (int j = 0; j < NL8; j++) {
        e[j] = __expf(lgs[j] - mx);
        sum += e[j];
    }
    sum += __shfl_xor_sync(0xffffffffu, sum, 4);
    sum += __shfl_xor_sync(0xffffffffu, sum, 2);
    sum += __shfl_xor_sync(0xffffffffu, sum, 1);
    const float inv = 1.f / sum;
    #pragma unroll
    for (int j = 0; j < NL8; j++) e[j] *= inv;

    const int gbase = lane & 24;
    const float* __restrict__ vp = vb + lo;
    float4 acc = make_float4(0.f, 0.f, 0.f, 0.f);

    #pragma unroll
    for (int n = 0; n < L; n++) {
        const int dy = n / KSZ - HALF, dx = n % KSZ - HALF;
        const float w = __shfl_sync(0xffffffffu, e[n >> 3], gbase + (n & 7));
        if (INTERIOR) {
            float4 vv = *(const float4*)(vp + (dy * 64 + dx) * DIL * HD);
            acc.x += w * vv.x; acc.y += w * vv.y;
            acc.z += w * vv.z; acc.w += w * vv.w;
        } else {
            const int ny = y + dy * DIL;
            const int nx = x + dx * DIL;
            if ((unsigned)ny < 64u && (unsigned)nx < 64u) {
                float4 vv = *(const float4*)(vb + (ny * 64 + nx) * HD + r * 4);
                acc.x += w * vv.x; acc.y += w * vv.y;
                acc.z += w * vv.z; acc.w += w * vv.w;
            }
        }
    }

    *(float4*)(g_attn + ((size_t)(b * HW + p)) * CDIM + head * HD + r * 4) = acc;
}

template <int KSZ, int DIL>
__device__ __forceinline__ void attn_quad_dispatch(int lane, int b, int head, int p0)
{
    constexpr int R = (KSZ / 2) * DIL;
    const int y = p0 >> 6, x0 = p0 & 63;
    if (y >= R && y < 64 - R && x0 >= R && x0 + 3 < 64 - R)
        attn_quad<KSZ, DIL, true>(lane, b, head, p0);
    else
        attn_quad<KSZ, DIL, false>(lane, b, head, p0);
}

__global__ __launch_bounds__(256) void attn_kernel()
{
    const int lane = threadIdx.x & 31;
    const int wid  = threadIdx.x >> 5;
    const int W    = blockIdx.x * 8 + wid;
    const int p0   = (W & 1023) * 4;
    const int head = (W >> 10) & 7;
    const int b    = W >> 13;

    if (head < 4)      attn_quad_dispatch<5, 1>(lane, b, head, p0);
    else if (head < 7) attn_quad_dispatch<7, 2>(lane, b, head, p0);
    else               attn_quad_dispatch<9, 3>(lane, b, head, p0);
}

// ---------------------------------------------------------------------------
// Kernel 3: output projection, tf32, 64x64 tile, k-chunk 32 (proven R8/R11
// config; epilogue already coalesced along p).
// ---------------------------------------------------------------------------
__global__ __launch_bounds__(256) void proj_gemm_kernel(
    const float* __restrict__ pw, const float* __restrict__ pb,
    float* __restrict__ out)
{
    __shared__ unsigned As[64][36];
    __shared__ unsigned Bs[64][36];

    const int tid  = threadIdx.x;
    const int row0 = blockIdx.y * 64;
    const int col0 = blockIdx.x * 64;
    const int b    = blockIdx.z;

    const int wid  = tid >> 5;
    const int lane = tid & 31;
    const int g = lane >> 2, t4 = lane & 3;
    const int m0 = (wid >> 2) * 32;
    const int n0 = (wid & 3) * 16;

    const int am = tid >> 2, ak = (tid & 3) * 8;

    const float* attb = g_attn + (size_t)b * HW * CDIM;
    float acc[2][2][4] = {};

    for (int k0 = 0; k0 < 256; k0 += 32) {
        {
            const float* src = pw + (size_t)(row0 + am) * 256 + k0 + ak;
            float4 v0 = *(const float4*)(src);
            float4 v1 = *(const float4*)(src + 4);
            *(uint4*)&As[am][ak]     = f2tf4(v0);
            *(uint4*)&As[am][ak + 4] = f2tf4(v1);
        }
        {
            const float* src = attb + (size_t)(col0 + am) * CDIM + k0 + ak;
            float4 v0 = *(const float4*)(src);
            float4 v1 = *(const float4*)(src + 4);
            *(uint4*)&Bs[am][ak]     = f2tf4(v0);
            *(uint4*)&Bs[am][ak + 4] = f2tf4(v1);
        }
        __syncthreads();
        #pragma unroll
        for (int ks = 0; ks < 4; ks++) {
            const int kk = ks * 8;
            unsigned a[2][4], bf[2][2];
            #pragma unroll
            for (int mi = 0; mi < 2; mi++) {
                const int mr = m0 + mi * 16;
                a[mi][0] = As[mr + g][kk + t4];
                a[mi][1] = As[mr + g + 8][kk + t4];
                a[mi][2] = As[mr + g][kk + t4 + 4];
                a[mi][3] = As[mr + g + 8][kk + t4 + 4];
            }
            #pragma unroll
            for (int ni = 0; ni < 2; ni++) {
                const int nc = n0 + ni * 8 + g;
                bf[ni][0] = Bs[nc][kk + t4];
                bf[ni][1] = Bs[nc][kk + t4 + 4];
            }
            #pragma unroll
            for (int mi = 0; mi < 2; mi++)
                #pragma unroll
                for (int ni = 0; ni < 2; ni++)
                    mma8(acc[mi][ni], a[mi], bf[ni]);
        }
        __syncthreads();
    }

    #pragma unroll
    for (int mi = 0; mi < 2; mi++) {
        const int ol = row0 + m0 + mi * 16 + g;
        const int oh = ol + 8;
        const float bl = pb[ol], bh = pb[oh];
        float* basel = out + ((size_t)b * CDIM + ol) * HW;
        float* baseh = out + ((size_t)b * CDIM + oh) * HW;
        #pragma unroll
        for (int ni = 0; ni < 2; ni++) {
            const int p = col0 + n0 + ni * 8 + 2 * t4;
            *(float2*)(basel + p) =
                make_float2(acc[mi][ni][0] + bl, acc[mi][ni][1] + bl);
            *(float2*)(baseh + p) =
                make_float2(acc[mi][ni][2] + bh, acc[mi][ni][3] + bh);
        }
    }
}

// ---------------------------------------------------------------------------
extern "C" void kernel_launch(void* const* d_in, const int* in_sizes, int n_in,
                              void* d_out, int out_size)
{
    const float* x   = (const float*)d_in[0];
    const float* w0  = (const float*)d_in[1];
    const float* bb0 = (const float*)d_in[2];
    const float* w1  = (const float*)d_in[3];
    const float* bb1 = (const float*)d_in[4];
    const float* w2  = (const float*)d_in[5];
    const float* bb2 = (const float*)d_in[6];
    const float* pw  = (const float*)d_in[7];
    const float* pb  = (const float*)d_in[8];
    float* out = (float*)d_out;

    qkv_gemm_kernel<<<dim3(HW / 64, 768 / 64, BATCH), 256>>>(
        x, w0, bb0, w1, bb1, w2, bb2);

    attn_kernel<<<(BATCH * NH * HW / 4) / 8, 256>>>();

    proj_gemm_kernel<<<dim3(HW / 64, CDIM / 64, BATCH), 256>>>(pw, pb, out);
}

// round 13
// speedup vs baseline: 1.0788x; 1.0788x over previous
#include <cuda_runtime.h>

#define HW     4096
#define WIDTH  64
#define CDIM   256
#define NH     8
#define HD     32
#define BATCH  2
#define SCALE  0.17677669529663687f

// Scratch (device globals; no allocation allowed)
__device__ float g_q[BATCH * NH * HW * HD];      // [b, head, p, d]
__device__ float g_k[BATCH * NH * HW * HD];      // [b, head, p, d]
__device__ float g_v[BATCH * NH * HW * HD];      // [b, head, p, d]
__device__ float g_attn[BATCH * HW * CDIM];      // [b, p, c]  c = head*32+d

// ---------------------------------------------------------------------------
// tf32 MMA helpers
// ---------------------------------------------------------------------------
__device__ __forceinline__ unsigned f2tf(float f)
{
    unsigned u;
    asm("cvt.rna.tf32.f32 %0, %1;" : "=r"(u) : "f"(f));
    return u;
}

__device__ __forceinline__ uint4 f2tf4(float4 v)
{
    uint4 u;
    u.x = f2tf(v.x); u.y = f2tf(v.y); u.z = f2tf(v.z); u.w = f2tf(v.w);
    return u;
}

__device__ __forceinline__ void mma8(float d[4], const unsigned a[4], const unsigned b[2])
{
    asm("mma.sync.aligned.m16n8k8.row.col.f32.tf32.tf32.f32 "
        "{%0,%1,%2,%3}, {%4,%5,%6,%7}, {%8,%9}, {%0,%1,%2,%3};"
        : "+f"(d[0]), "+f"(d[1]), "+f"(d[2]), "+f"(d[3])
        : "r"(a[0]), "r"(a[1]), "r"(a[2]), "r"(a[3]),
          "r"(b[0]), "r"(b[1]));
}

// ---------------------------------------------------------------------------
// Kernel 1: QKV projection, tf32, 64x64 tile, k-chunk 32 (proven R11 config).
// ---------------------------------------------------------------------------
__global__ __launch_bounds__(256) void qkv_gemm_kernel(
    const float* __restrict__ x,
    const float* __restrict__ w0, const float* __restrict__ bb0,
    const float* __restrict__ w1, const float* __restrict__ bb1,
    const float* __restrict__ w2, const float* __restrict__ bb2)
{
    __shared__ unsigned As[64][36];
    __shared__ unsigned Bs[32][72];
    __shared__ const float* Arow[64];
    __shared__ float* rowDst[64];
    __shared__ float biasS[64];

    const int tid  = threadIdx.x;
    const int row0 = blockIdx.y * 64;
    const int col0 = blockIdx.x * 64;
    const int b    = blockIdx.z;

    if (tid < 64) {
        int M = row0 + tid;
        int t = M >> 8;
        int rem = M & 255;
        int head = rem >> 5, d = rem & 31;
        const float* w; const float* bb;
        if (head < 4)      { w = w0; bb = bb0; }
        else if (head < 7) { w = w1; bb = bb1; }
        else               { w = w2; bb = bb2; }
        Arow[tid]  = w + (size_t)(t * 256 + rem) * 256;
        biasS[tid] = bb[t * 256 + rem];
        float* dst = (t == 0) ? g_q : (t == 1) ? g_k : g_v;
        rowDst[tid] = dst + ((size_t)(b * NH + head) * HW) * HD + d;
    }
    __syncthreads();

    const int wid  = tid >> 5;
    const int lane = tid & 31;
    const int g = lane >> 2, t4 = lane & 3;
    const int m0 = (wid >> 2) * 32;
    const int n0 = (wid & 3) * 16;

    const int am = tid >> 2, ak = (tid & 3) * 8;
    const int bk = tid >> 3, bn = (tid & 7) * 8;

    const float* xb = x + (size_t)b * CDIM * HW;
    float acc[2][2][4] = {};

    for (int k0 = 0; k0 < 256; k0 += 32) {
        {
            const float* src = Arow[am] + k0 + ak;
            float4 v0 = *(const float4*)(src);
            float4 v1 = *(const float4*)(src + 4);
            *(uint4*)&As[am][ak]     = f2tf4(v0);
            *(uint4*)&As[am][ak + 4] = f2tf4(v1);
        }
        {
            const float* src = xb + (size_t)(k0 + bk) * HW + col0 + bn;
            float4 v0 = *(const float4*)(src);
            float4 v1 = *(const float4*)(src + 4);
            *(uint4*)&Bs[bk][bn]     = f2tf4(v0);
            *(uint4*)&Bs[bk][bn + 4] = f2tf4(v1);
        }
        __syncthreads();
        #pragma unroll
        for (int ks = 0; ks < 4; ks++) {
            const int kk = ks * 8;
            unsigned a[2][4], bf[2][2];
            #pragma unroll
            for (int mi = 0; mi < 2; mi++) {
                const int mr = m0 + mi * 16;
                a[mi][0] = As[mr + g][kk + t4];
                a[mi][1] = As[mr + g + 8][kk + t4];
                a[mi][2] = As[mr + g][kk + t4 + 4];
                a[mi][3] = As[mr + g + 8][kk + t4 + 4];
            }
            #pragma unroll
            for (int ni = 0; ni < 2; ni++) {
                const int nc = n0 + ni * 8 + g;
                bf[ni][0] = Bs[kk + t4][nc];
                bf[ni][1] = Bs[kk + t4 + 4][nc];
            }
            #pragma unroll
            for (int mi = 0; mi < 2; mi++)
                #pragma unroll
                for (int ni = 0; ni < 2; ni++)
                    mma8(acc[mi][ni], a[mi], bf[ni]);
        }
        __syncthreads();
    }

    #pragma unroll
    for (int mi = 0; mi < 2; mi++) {
        const int rl = m0 + mi * 16 + g;
        const int rh = rl + 8;
        float* dl = rowDst[rl]; const float bl = biasS[rl];
        float* dh = rowDst[rh]; const float bh = biasS[rh];
        #pragma unroll
        for (int ni = 0; ni < 2; ni++) {
            const int p = col0 + n0 + ni * 8 + 2 * t4;
            dl[(size_t)p * HD]       = acc[mi][ni][0] + bl;
            dl[(size_t)(p + 1) * HD] = acc[mi][ni][1] + bl;
            dh[(size_t)p * HD]       = acc[mi][ni][2] + bh;
            dh[(size_t)(p + 1) * HD] = acc[mi][ni][3] + bh;
        }
    }
}

// ---------------------------------------------------------------------------
// Kernel 2: neighborhood attention, quad-pixel warps. One warp = 4 adjacent
// pixels; 8 lanes per pixel; float4 dims per lane. Logits: per 8 neighbors,
// each lane computes its partial dot for all 8, then one 7-shuffle butterfly
// (masks 4/2/1, within the 8-lane pixel group) reduces all 8 simultaneously,
// landing neighbor base+r on lane r (the existing lgs slot layout).
// OOB neighbors keep logit = 0 inside the softmax (F.unfold zero padding);
// slots past L keep -1e30 -> exp = 0.
// ---------------------------------------------------------------------------
template <int KSZ, int DIL, bool INTERIOR>
__device__ __forceinline__ void attn_quad(int lane, int b, int head, int p0)
{
    constexpr int L = KSZ * KSZ;
    constexpr int NL8 = (L + 7) / 8;
    constexpr int HALF = KSZ / 2;

    const int r = lane & 7;
    const int g = lane >> 3;
    const int p = p0 + g;
    const int y = p0 >> 6;
    const int x = (p0 & 63) + g;

    const int hb = ((b * NH + head) * HW) * HD;
    const float* __restrict__ kb = g_k + hb;
    const float* __restrict__ vb = g_v + hb;
    const int lo = p * HD + r * 4;

    float4 qv = *(const float4*)(g_q + hb + lo);
    qv.x *= SCALE; qv.y *= SCALE; qv.z *= SCALE; qv.w *= SCALE;

    const float* __restrict__ kp = kb + lo;

    float lgs[NL8];
    #pragma unroll
    for (int pass = 0; pass < NL8; pass++) {
        float v[8];
        #pragma unroll
        for (int j = 0; j < 8; j++) {
            const int n = pass * 8 + j;
            float4 kv = make_float4(0.f, 0.f, 0.f, 0.f);
            if (n < L) {
                const int dy = n / KSZ - HALF, dx = n % KSZ - HALF;
                if (INTERIOR) {
                    kv = *(const float4*)(kp + (dy * 64 + dx) * DIL * HD);
                } else {
                    const int ny = y + dy * DIL;
                    const int nx = x + dx * DIL;
                    if ((unsigned)ny < 64u && (unsigned)nx < 64u)
                        kv = *(const float4*)(kb + (ny * 64 + nx) * HD + r * 4);
                }
            }
            v[j] = qv.x * kv.x + qv.y * kv.y + qv.z * kv.z + qv.w * kv.w;
        }
        // Butterfly transpose-reduction over the 8-lane pixel group:
        // afterwards v[0] on lane r holds the full dot of neighbor pass*8+r.
        #pragma unroll
        for (int m = 4; m >= 1; m >>= 1) {
            const bool up = (r & m) != 0;
            #pragma unroll
            for (int j = 0; j < m; j++) {
                float send = up ? v[j] : v[j + m];
                float recv = __shfl_xor_sync(0xffffffffu, send, m);
                v[j] = (up ? v[j + m] : v[j]) + recv;
            }
        }
        lgs[pass] = (pass * 8 + r < L) ? v[0] : -1e30f;
    }

    float mx = lgs[0];
    #pragma unroll
    for (int j = 1; j < NL8; j++) mx = fmaxf(mx, lgs[j]);
    mx = fmaxf(mx, __shfl_xor_sync(0xffffffffu, mx, 4));
    mx = fmaxf(mx, __shfl_xor_sync(0xffffffffu, mx, 2));
    mx = fmaxf(mx, __shfl_xor_sync(0xffffffffu, mx, 1));

    float e[NL8];
    float sum = 0.f;
    #pragma unroll
    for (int j = 0; j < NL8; j++) {
        e[j] = __expf(lgs[j] - mx);
        sum += e[j];
    }
    sum += __shfl_xor_sync(0xffffffffu, sum, 4);
    sum += __shfl_xor_sync(0xffffffffu, sum, 2);
    sum += __shfl_xor_sync(0xffffffffu, sum, 1);
    const float inv = 1.f / sum;
    #pragma unroll
    for (int j = 0; j < NL8; j++) e[j] *= inv;

    const int gbase = lane & 24;
    const float* __restrict__ vp = vb + lo;
    float4 acc = make_float4(0.f, 0.f, 0.f, 0.f);

    #pragma unroll
    for (int n = 0; n < L; n++) {
        const int dy = n / KSZ - HALF, dx = n % KSZ - HALF;
        const float w = __shfl_sync(0xffffffffu, e[n >> 3], gbase + (n & 7));
        if (INTERIOR) {
            float4 vv = *(const float4*)(vp + (dy * 64 + dx) * DIL * HD);
            acc.x += w * vv.x; acc.y += w * vv.y;
            acc.z += w * vv.z; acc.w += w * vv.w;
        } else {
            const int ny = y + dy * DIL;
            const int nx = x + dx * DIL;
            if ((unsigned)ny < 64u && (unsigned)nx < 64u) {
                float4 vv = *(const float4*)(vb + (ny * 64 + nx) * HD + r * 4);
                acc.x += w * vv.x; acc.y += w * vv.y;
                acc.z += w * vv.z; acc.w += w * vv.w;
            }
        }
    }

    *(float4*)(g_attn + ((size_t)(b * HW + p)) * CDIM + head * HD + r * 4) = acc;
}

template <int KSZ, int DIL>
__device__ __forceinline__ void attn_quad_dispatch(int lane, int b, int head, int p0)
{
    constexpr int R = (KSZ / 2) * DIL;
    const int y = p0 >> 6, x0 = p0 & 63;
    if (y >= R && y < 64 - R && x0 >= R && x0 + 3 < 64 - R)
        attn_quad<KSZ, DIL, true>(lane, b, head, p0);
    else
        attn_quad<KSZ, DIL, false>(lane, b, head, p0);
}

__global__ __launch_bounds__(256) void attn_kernel()
{
    const int lane = threadIdx.x & 31;
    const int wid  = threadIdx.x >> 5;
    const int W    = blockIdx.x * 8 + wid;
    const int p0   = (W & 1023) * 4;
    const int head = (W >> 10) & 7;
    const int b    = W >> 13;

    if (head < 4)      attn_quad_dispatch<5, 1>(lane, b, head, p0);
    else if (head < 7) attn_quad_dispatch<7, 2>(lane, b, head, p0);
    else               attn_quad_dispatch<9, 3>(lane, b, head, p0);
}

// ---------------------------------------------------------------------------
// Kernel 3: output projection, tf32, 64x64 tile, k-chunk 32 (proven R11
// config).
// ---------------------------------------------------------------------------
__global__ __launch_bounds__(256) void proj_gemm_kernel(
    const float* __restrict__ pw, const float* __restrict__ pb,
    float* __restrict__ out)
{
    __shared__ unsigned As[64][36];
    __shared__ unsigned Bs[64][36];

    const int tid  = threadIdx.x;
    const int row0 = blockIdx.y * 64;
    const int col0 = blockIdx.x * 64;
    const int b    = blockIdx.z;

    const int wid  = tid >> 5;
    const int lane = tid & 31;
    const int g = lane >> 2, t4 = lane & 3;
    const int m0 = (wid >> 2) * 32;
    const int n0 = (wid & 3) * 16;

    const int am = tid >> 2, ak = (tid & 3) * 8;

    const float* attb = g_attn + (size_t)b * HW * CDIM;
    float acc[2][2][4] = {};

    for (int k0 = 0; k0 < 256; k0 += 32) {
        {
            const float* src = pw + (size_t)(row0 + am) * 256 + k0 + ak;
            float4 v0 = *(const float4*)(src);
            float4 v1 = *(const float4*)(src + 4);
            *(uint4*)&As[am][ak]     = f2tf4(v0);
            *(uint4*)&As[am][ak + 4] = f2tf4(v1);
        }
        {
            const float* src = attb + (size_t)(col0 + am) * CDIM + k0 + ak;
            float4 v0 = *(const float4*)(src);
            float4 v1 = *(const float4*)(src + 4);
            *(uint4*)&Bs[am][ak]     = f2tf4(v0);
            *(uint4*)&Bs[am][ak + 4] = f2tf4(v1);
        }
        __syncthreads();
        #pragma unroll
        for (int ks = 0; ks < 4; ks++) {
            const int kk = ks * 8;
            unsigned a[2][4], bf[2][2];
            #pragma unroll
            for (int mi = 0; mi < 2; mi++) {
                const int mr = m0 + mi * 16;
                a[mi][0] = As[mr + g][kk + t4];
                a[mi][1] = As[mr + g + 8][kk + t4];
                a[mi][2] = As[mr + g][kk + t4 + 4];
                a[mi][3] = As[mr + g + 8][kk + t4 + 4];
            }
            #pragma unroll
            for (int ni = 0; ni < 2; ni++) {
                const int nc = n0 + ni * 8 + g;
                bf[ni][0] = Bs[nc][kk + t4];
                bf[ni][1] = Bs[nc][kk + t4 + 4];
            }
            #pragma unroll
            for (int mi = 0; mi < 2; mi++)
                #pragma unroll
                for (int ni = 0; ni < 2; ni++)
                    mma8(acc[mi][ni], a[mi], bf[ni]);
        }
        __syncthreads();
    }

    #pragma unroll
    for (int mi = 0; mi < 2; mi++) {
        const int ol = row0 + m0 + mi * 16 + g;
        const int oh = ol + 8;
        const float bl = pb[ol], bh = pb[oh];
        float* basel = out + ((size_t)b * CDIM + ol) * HW;
        float* baseh = out + ((size_t)b * CDIM + oh) * HW;
        #pragma unroll
        for (int ni = 0; ni < 2; ni++) {
            const int p = col0 + n0 + ni * 8 + 2 * t4;
            *(float2*)(basel + p) =
                make_float2(acc[mi][ni][0] + bl, acc[mi][ni][1] + bl);
            *(float2*)(baseh + p) =
                make_float2(acc[mi][ni][2] + bh, acc[mi][ni][3] + bh);
        }
    }
}

// ---------------------------------------------------------------------------
extern "C" void kernel_launch(void* const* d_in, const int* in_sizes, int n_in,
                              void* d_out, int out_size)
{
    const float* x   = (const float*)d_in[0];
    const float* w0  = (const float*)d_in[1];
    const float* bb0 = (const float*)d_in[2];
    const float* w1  = (const float*)d_in[3];
    const float* bb1 = (const float*)d_in[4];
    const float* w2  = (const float*)d_in[5];
    const float* bb2 = (const float*)d_in[6];
    const float* pw  = (const float*)d_in[7];
    const float* pb  = (const float*)d_in[8];
    float* out = (float*)d_out;

    qkv_gemm_kernel<<<dim3(HW / 64, 768 / 64, BATCH), 256>>>(
        x, w0, bb0, w1, bb1, w2, bb2);

    attn_kernel<<<(BATCH * NH * HW / 4) / 8, 256>>>();

    proj_gemm_kernel<<<dim3(HW / 64, CDIM / 64, BATCH), 256>>>(pw, pb, out);
}